// round 6
// baseline (speedup 1.0000x reference)
#include <cuda_runtime.h>
#include <cstdint>

// Problem dims (hardcoded; all tile-divisible)
#define NB   4
#define NT   2048
#define NC   1024
#define NH   16
#define NDK  64
#define NBH  (NB*NH)      // 64
#define NM   (NB*NT)      // 8192

// Scratch (static device arrays: allocation-free)
__device__ __align__(128) float g_q[(size_t)NBH*NT*NDK];
__device__ __align__(128) float g_k[(size_t)NBH*NT*NDK];
__device__ __align__(128) float g_v[(size_t)NBH*NT*NDK];
__device__ __align__(128) float g_attn[(size_t)NM*NC];
// tf32-pre-rounded copies of the inputs (GEMM mainloops become cvt-free)
__device__ __align__(128) float g_xr[(size_t)NM*NC];
__device__ __align__(128) float g_wqkv[(size_t)3*NC*NC];
__device__ __align__(128) float g_wo[(size_t)NC*NC];

// ---------------- PTX helpers ----------------
__device__ __forceinline__ void cpa16(uint32_t s, const void* g) {
    asm volatile("cp.async.cg.shared.global [%0], [%1], 16;" :: "r"(s), "l"(g));
}
__device__ __forceinline__ void cp_commit() { asm volatile("cp.async.commit_group;"); }
template<int N> __device__ __forceinline__ void cp_wait() {
    asm volatile("cp.async.wait_group %0;" :: "n"(N));
}
__device__ __forceinline__ void mma_tf32(float* c,
    uint32_t a0, uint32_t a1, uint32_t a2, uint32_t a3,
    uint32_t b0, uint32_t b1)
{
    asm volatile(
        "mma.sync.aligned.m16n8k8.row.col.f32.tf32.tf32.f32 "
        "{%0,%1,%2,%3},{%4,%5,%6,%7},{%8,%9},{%0,%1,%2,%3};"
        : "+f"(c[0]), "+f"(c[1]), "+f"(c[2]), "+f"(c[3])
        : "r"(a0), "r"(a1), "r"(a2), "r"(a3), "r"(b0), "r"(b1));
}
// rna round to tf32 (result in fp32 layout)
__device__ __forceinline__ float tf32_rna(float x) {
    uint32_t h;
    asm("cvt.rna.tf32.f32 %0, %1;" : "=r"(h) : "f"(x));
    return __uint_as_float(h);
}
__device__ __forceinline__ uint32_t tf32_rna_u(float x) {
    uint32_t h;
    asm("cvt.rna.tf32.f32 %0, %1;" : "=r"(h) : "f"(x));
    return h;
}
__device__ __forceinline__ float ex2f(float x) {
    float y;
    asm("ex2.approx.f32 %0, %1;" : "=f"(y) : "f"(x));
    return y;
}

// ---------------- Pre-round inputs to tf32 ----------------
// sel: 0 -> g_xr, 1 -> g_wqkv, 2 -> g_wo.  n4 float4 elements.
__global__ void __launch_bounds__(256)
round_pre(const float4* __restrict__ src, int n4, int sel)
{
    float* dstf = (sel == 0) ? g_xr : (sel == 1) ? g_wqkv : g_wo;
    int idx = blockIdx.x * 256 + threadIdx.x;
    if (idx < n4) {
        float4 v = src[idx];
        v.x = tf32_rna(v.x); v.y = tf32_rna(v.y);
        v.z = tf32_rna(v.z); v.w = tf32_rna(v.w);
        ((float4*)dstf)[idx] = v;
    }
}

// ---------------- GEMM: C[M,N] = A[M,K] * B[N,K]^T (1x tf32, operands pre-rounded)
// MODE 1: A=g_xr, B=g_wqkv; scatter QKV (rna-rounded) into g_q/g_k/g_v.
// MODE 2: A=g_attn (tf32-rounded by flash), B=g_wo; plain write to Cm.
// Block 128x256x32, 256 threads, warps 2(m) x 4(n), warp tile 64x64.
// smem stage = As[128][36] + Bs[256][36] (uint32 words), double buffered.
#define GAW  4608            // A words per stage (128*36)
#define GBW  9216            // B words per stage (256*36)
#define GSTG (GAW + GBW)     // 13824 words per stage
#define GPAD 36

template<int MODE>
__global__ void __launch_bounds__(256, 1)
gemm_tf32(float* __restrict__ Cm, int M, int N, int K)
{
    extern __shared__ uint32_t sm[];
    const int tid  = threadIdx.x;
    const int warp = tid >> 5, lane = tid & 31;
    const int gid  = lane >> 2, tig = lane & 3;
    const int wm = warp >> 2, wn = warp & 3;
    const int m0 = blockIdx.y * 128, n0 = blockIdx.x * 256;

    const float* Aeff = (MODE == 1) ? g_xr   : g_attn;
    const float* Beff = (MODE == 1) ? g_wqkv : g_wo;
    const uint32_t smb = (uint32_t)__cvta_generic_to_shared(sm);

    float acc[4][8][4];
#pragma unroll
    for (int i = 0; i < 4; i++)
#pragma unroll
        for (int j = 0; j < 8; j++)
#pragma unroll
            for (int r = 0; r < 4; r++) acc[i][j][r] = 0.f;

    auto load_tile = [&](int stage, int k0) {
        uint32_t base = smb + stage * GSTG * 4;
        // A: 128 rows x 32 cols = 1024 float4
#pragma unroll
        for (int it = 0; it < 4; it++) {
            int idx = tid + it * 256;
            int r  = idx >> 3;
            int c4 = (idx & 7) * 4;
            cpa16(base + (uint32_t)(r * GPAD + c4) * 4,
                  Aeff + (size_t)(m0 + r) * K + k0 + c4);
        }
        // B: 256 rows x 32 cols = 2048 float4
#pragma unroll
        for (int it = 0; it < 8; it++) {
            int idx = tid + it * 256;
            int r  = idx >> 3;
            int c4 = (idx & 7) * 4;
            cpa16(base + (uint32_t)(GAW + r * GPAD + c4) * 4,
                  Beff + (size_t)(n0 + r) * K + k0 + c4);
        }
        cp_commit();
    };

    const int NTI = K / 32;
    load_tile(0, 0);

    for (int kt = 0; kt < NTI; kt++) {
        if (kt + 1 < NTI) { load_tile((kt + 1) & 1, (kt + 1) * 32); cp_wait<1>(); }
        else              { cp_wait<0>(); }
        __syncthreads();

        const uint32_t* As = sm + (kt & 1) * GSTG;
        const uint32_t* Bs = As + GAW;
#pragma unroll
        for (int kk = 0; kk < 4; kk++) {
            uint32_t a[4][4], b[8][2];
#pragma unroll
            for (int i = 0; i < 4; i++) {
                const uint32_t* ap = As + (wm * 64 + i * 16 + gid) * GPAD + kk * 8 + tig;
                a[i][0] = ap[0];
                a[i][1] = ap[8 * GPAD];
                a[i][2] = ap[4];
                a[i][3] = ap[8 * GPAD + 4];
            }
#pragma unroll
            for (int j = 0; j < 8; j++) {
                const uint32_t* bp = Bs + (wn * 64 + j * 8 + gid) * GPAD + kk * 8 + tig;
                b[j][0] = bp[0];
                b[j][1] = bp[4];
            }
#pragma unroll
            for (int i = 0; i < 4; i++)
#pragma unroll
                for (int j = 0; j < 8; j++)
                    mma_tf32(acc[i][j], a[i][0], a[i][1], a[i][2], a[i][3],
                             b[j][0], b[j][1]);
        }
        __syncthreads();
    }

    // Epilogue
#pragma unroll
    for (int i = 0; i < 4; i++) {
#pragma unroll
        for (int j = 0; j < 8; j++) {
            int r0 = m0 + wm * 64 + i * 16 + gid;
            int cg = n0 + wn * 64 + j * 8 + tig * 2;
            if (MODE == 2) {
                float2 v0 = make_float2(acc[i][j][0], acc[i][j][1]);
                float2 v1 = make_float2(acc[i][j][2], acc[i][j][3]);
                *(float2*)&Cm[(size_t)r0 * N + cg]       = v0;
                *(float2*)&Cm[(size_t)(r0 + 8) * N + cg] = v1;
            } else {
                int s   = cg >> 10;
                int rem = cg & 1023;
                int h   = rem >> 6;
                int d   = rem & 63;
                float* dst = (s == 0) ? g_q : (s == 1) ? g_k : g_v;
#pragma unroll
                for (int half = 0; half < 2; half++) {
                    int r = r0 + half * 8;
                    int b2 = r >> 11, t = r & 2047;
                    // rna-round to tf32 so flash can use 1x mma exactly
                    float2 v = make_float2(tf32_rna(acc[i][j][half * 2]),
                                           tf32_rna(acc[i][j][half * 2 + 1]));
                    *(float2*)&dst[((size_t)(b2 * NH + h) * NT + t) * NDK + d] = v;
                }
            }
        }
    }
}

// ---------------- Flash attention (1x tf32; M=32/warp, kv-tile 64) ------------
// grid (8 q-tiles of 256, 64 bh), 256 threads (8 warps).
// Warp w owns q-rows w*32 .. w*32+31 (two 16-row m-frags sharing B-frags).
// smem (uint32 words): Qs[256][68] @0, Ks[2][64][68] @17408/@21760,
//                      Vs[2][64][72] @26112/@30720. Total 141312 bytes.
#define KS_OFF0 17408
#define KS_OFF1 21760
#define VS_OFF0 26112
#define VS_OFF1 30720
#define FL_SMEM 141312
#define NKT     32            // 2048 / 64 kv tiles

__global__ void __launch_bounds__(256)
flash_attn()
{
    extern __shared__ uint32_t sm[];
    const int tid  = threadIdx.x;
    const int warp = tid >> 5, lane = tid & 31;
    const int gid  = lane >> 2, tig = lane & 3;
    const int bh = blockIdx.y, qt = blockIdx.x;
    const int qrow = warp * 32;

    const float* Qg = g_q + ((size_t)bh * NT + qt * 256) * NDK;
    const float* Kg = g_k + (size_t)bh * NT * NDK;
    const float* Vg = g_v + (size_t)bh * NT * NDK;

    const uint32_t smb = (uint32_t)__cvta_generic_to_shared(sm);

    auto load_kv = [&](int stage, int kt) {
        uint32_t koff = stage ? KS_OFF1 : KS_OFF0;
        uint32_t voff = stage ? VS_OFF1 : VS_OFF0;
        const float* kp = Kg + (size_t)kt * 64 * NDK;
        const float* vp = Vg + (size_t)kt * 64 * NDK;
#pragma unroll
        for (int it = 0; it < 4; it++) {
            int idx = tid + it * 256;        // 1024 float4 per tile
            int r  = idx >> 4;
            int c4 = (idx & 15) * 4;
            cpa16(smb + (koff + (uint32_t)(r * 68 + c4)) * 4, kp + r * 64 + c4);
            cpa16(smb + (voff + (uint32_t)(r * 72 + c4)) * 4, vp + r * 64 + c4);
        }
    };

    // Prologue: Q (256 rows) + tile0 K/V in group 0
#pragma unroll
    for (int it = 0; it < 16; it++) {
        int idx = tid + it * 256;            // 4096 float4
        int r  = idx >> 4;
        int c4 = (idx & 15) * 4;
        cpa16(smb + (uint32_t)(r * 68 + c4) * 4, Qg + r * 64 + c4);
    }
    load_kv(0, 0);
    cp_commit();

    float o[2][8][4];
#pragma unroll
    for (int mf = 0; mf < 2; mf++)
#pragma unroll
        for (int j = 0; j < 8; j++)
#pragma unroll
            for (int r = 0; r < 4; r++) o[mf][j][r] = 0.f;
    float mrow[2][2] = { { -1e30f, -1e30f }, { -1e30f, -1e30f } };
    float lrow[2][2] = { { 0.f, 0.f }, { 0.f, 0.f } };

    const float SCL = 0.125f * 1.4426950408889634f;   // (1/sqrt(64)) * log2(e)

    for (int kt = 0; kt < NKT; kt++) {
        const int st = kt & 1;
        if (kt < NKT - 1) { load_kv((kt + 1) & 1, kt + 1); cp_commit(); cp_wait<1>(); }
        else              { cp_wait<0>(); }
        __syncthreads();

        const uint32_t* Ks = sm + (st ? KS_OFF1 : KS_OFF0);
        const uint32_t* Vs = sm + (st ? VS_OFF1 : VS_OFF0);
        const uint32_t* Qs = sm;

        // S = Q * K^T : 32 rows x 64 keys per warp; B-frags shared by 2 m-frags.
        float s[2][8][4];
#pragma unroll
        for (int mf = 0; mf < 2; mf++)
#pragma unroll
            for (int j = 0; j < 8; j++)
#pragma unroll
                for (int r = 0; r < 4; r++) s[mf][j][r] = 0.f;

#pragma unroll
        for (int kk = 0; kk < 8; kk++) {
            const uint32_t* ap = Qs + (qrow + gid) * 68 + kk * 8 + tig;
            uint32_t a0[4], a1[4];
            a0[0] = ap[0];            a0[1] = ap[8 * 68];
            a0[2] = ap[4];            a0[3] = ap[8 * 68 + 4];
            a1[0] = ap[16 * 68];      a1[1] = ap[24 * 68];
            a1[2] = ap[16 * 68 + 4];  a1[3] = ap[24 * 68 + 4];
#pragma unroll
            for (int j = 0; j < 8; j++) {
                const uint32_t* bp = Ks + (j * 8 + gid) * 68 + kk * 8 + tig;
                uint32_t b0 = bp[0], b1 = bp[4];
                mma_tf32(s[0][j], a0[0], a0[1], a0[2], a0[3], b0, b1);
                mma_tf32(s[1][j], a1[0], a1[1], a1[2], a1[3], b0, b1);
            }
        }

        // Online softmax per m-frag (log2-domain: p = 2^(s*SCL - m*SCL)).
        float alpha[2][2];
#pragma unroll
        for (int mf = 0; mf < 2; mf++) {
            float mnew[2], rsum[2];
#pragma unroll
            for (int rr = 0; rr < 2; rr++) {
                float v = -1e30f;
#pragma unroll
                for (int j = 0; j < 8; j++)
                    v = fmaxf(v, fmaxf(s[mf][j][2 * rr], s[mf][j][2 * rr + 1]));
                v = fmaxf(v, __shfl_xor_sync(0xffffffffu, v, 1));
                v = fmaxf(v, __shfl_xor_sync(0xffffffffu, v, 2));
                mnew[rr]  = fmaxf(mrow[mf][rr], v);
                alpha[mf][rr] = ex2f((mrow[mf][rr] - mnew[rr]) * SCL);
                rsum[rr]  = 0.f;
            }
            float m2_0 = mnew[0] * SCL;
            float m2_1 = mnew[1] * SCL;
#pragma unroll
            for (int j = 0; j < 8; j++) {
                float p0 = ex2f(fmaf(s[mf][j][0], SCL, -m2_0));
                float p1 = ex2f(fmaf(s[mf][j][1], SCL, -m2_0));
                float p2 = ex2f(fmaf(s[mf][j][2], SCL, -m2_1));
                float p3 = ex2f(fmaf(s[mf][j][3], SCL, -m2_1));
                s[mf][j][0] = p0; s[mf][j][1] = p1;
                s[mf][j][2] = p2; s[mf][j][3] = p3;
                rsum[0] += p0 + p1;
                rsum[1] += p2 + p3;
            }
#pragma unroll
            for (int rr = 0; rr < 2; rr++) {
                float v = rsum[rr];
                v += __shfl_xor_sync(0xffffffffu, v, 1);
                v += __shfl_xor_sync(0xffffffffu, v, 2);
                lrow[mf][rr] = lrow[mf][rr] * alpha[mf][rr] + v;
                mrow[mf][rr] = mnew[rr];
            }
#pragma unroll
            for (int j = 0; j < 8; j++) {
                o[mf][j][0] *= alpha[mf][0]; o[mf][j][1] *= alpha[mf][0];
                o[mf][j][2] *= alpha[mf][1]; o[mf][j][3] *= alpha[mf][1];
            }
        }

        // O += P * V (1x tf32; V pre-rounded, P rna-rounded after shuffle).
        // B-frags (V) shared by both m-frags.
        const int base = lane & ~3;
        const int lo_l = base + (tig >> 1);
        const int hi_l = lo_l + 2;
        const bool odd = (tig & 1);
#pragma unroll
        for (int kk = 0; kk < 8; kk++) {
            uint32_t aF[2][4];
#pragma unroll
            for (int mf = 0; mf < 2; mf++) {
                float q0 = __shfl_sync(0xffffffffu, s[mf][kk][0], lo_l);
                float q1 = __shfl_sync(0xffffffffu, s[mf][kk][1], lo_l);
                float q2 = __shfl_sync(0xffffffffu, s[mf][kk][2], lo_l);
                float q3 = __shfl_sync(0xffffffffu, s[mf][kk][3], lo_l);
                float r0 = __shfl_sync(0xffffffffu, s[mf][kk][0], hi_l);
                float r1 = __shfl_sync(0xffffffffu, s[mf][kk][1], hi_l);
                float r2 = __shfl_sync(0xffffffffu, s[mf][kk][2], hi_l);
                float r3 = __shfl_sync(0xffffffffu, s[mf][kk][3], hi_l);
                aF[mf][0] = tf32_rna_u(odd ? q1 : q0);
                aF[mf][1] = tf32_rna_u(odd ? q3 : q2);
                aF[mf][2] = tf32_rna_u(odd ? r1 : r0);
                aF[mf][3] = tf32_rna_u(odd ? r3 : r2);
            }
#pragma unroll
            for (int j = 0; j < 8; j++) {
                const uint32_t* bp = Vs + (kk * 8 + tig) * 72 + j * 8 + gid;
                uint32_t b0 = bp[0], b1 = bp[4 * 72];
                mma_tf32(o[0][j], aF[0][0], aF[0][1], aF[0][2], aF[0][3], b0, b1);
                mma_tf32(o[1][j], aF[1][0], aF[1][1], aF[1][2], aF[1][3], b0, b1);
            }
        }
        __syncthreads();
    }

    // Epilogue: O / l -> g_attn[b][t][h*64+d], rna-rounded to tf32 so the
    // output projection's A operand needs no cvt.
    const int b = bh >> 4, h = bh & 15;
#pragma unroll
    for (int mf = 0; mf < 2; mf++) {
        const float inv0 = 1.f / lrow[mf][0];
        const float inv1 = 1.f / lrow[mf][1];
        const int t0 = qt * 256 + qrow + mf * 16 + gid;
#pragma unroll
        for (int j = 0; j < 8; j++) {
            int d = j * 8 + tig * 2;
            float2 v0 = make_float2(tf32_rna(o[mf][j][0] * inv0), tf32_rna(o[mf][j][1] * inv0));
            float2 v1 = make_float2(tf32_rna(o[mf][j][2] * inv1), tf32_rna(o[mf][j][3] * inv1));
            *(float2*)&g_attn[(size_t)(b * NT + t0)     * NC + h * 64 + d] = v0;
            *(float2*)&g_attn[(size_t)(b * NT + t0 + 8) * NC + h * 64 + d] = v1;
        }
    }
}

// ---------------- launch ----------------
extern "C" void kernel_launch(void* const* d_in, const int* in_sizes, int n_in,
                              void* d_out, int out_size)
{
    const float* x     = (const float*)d_in[0];
    const float* w_qkv = (const float*)d_in[1];
    const float* w_o   = (const float*)d_in[2];
    float* out = (float*)d_out;

    cudaFuncSetAttribute(gemm_tf32<1>, cudaFuncAttributeMaxDynamicSharedMemorySize, 2 * GSTG * 4);
    cudaFuncSetAttribute(gemm_tf32<2>, cudaFuncAttributeMaxDynamicSharedMemorySize, 2 * GSTG * 4);
    cudaFuncSetAttribute(flash_attn,   cudaFuncAttributeMaxDynamicSharedMemorySize, FL_SMEM);

    // 0) pre-round inputs to tf32 (exact operands everywhere downstream)
    round_pre<<<(NM * NC / 4 + 255) / 256, 256>>>((const float4*)x,     NM * NC / 4,     0);
    round_pre<<<(3 * NC * NC / 4 + 255) / 256, 256>>>((const float4*)w_qkv, 3 * NC * NC / 4, 1);
    round_pre<<<(NC * NC / 4 + 255) / 256, 256>>>((const float4*)w_o,   NC * NC / 4,     2);

    // 1) QKV projection: [8192,1024] x [3072,1024]^T, scatter to g_q/g_k/g_v
    gemm_tf32<1><<<dim3(3072 / 256, NM / 128), 256, 2 * GSTG * 4>>>(
        nullptr, NM, 3 * NC, NC);

    // 2) attention (1x tf32 on pre-rounded operands)
    flash_attn<<<dim3(NT / 256, NBH), 256, FL_SMEM>>>();

    // 3) output projection: g_attn[8192,1024] x w_o[1024,1024]^T -> out
    gemm_tf32<2><<<dim3(NC / 256, NM / 128), 256, 2 * GSTG * 4>>>(
        out, NM, NC, NC);
}

// round 7
// speedup vs baseline: 1.0838x; 1.0838x over previous
#include <cuda_runtime.h>
#include <cstdint>

// Problem dims (hardcoded; all tile-divisible)
#define NB   4
#define NT   2048
#define NC   1024
#define NH   16
#define NDK  64
#define NBH  (NB*NH)      // 64
#define NM   (NB*NT)      // 8192

// Scratch (static device arrays: allocation-free)
__device__ __align__(128) float g_q[(size_t)NBH*NT*NDK];
__device__ __align__(128) float g_k[(size_t)NBH*NT*NDK];
__device__ __align__(128) float g_v[(size_t)NBH*NT*NDK];
__device__ __align__(128) float g_attn[(size_t)NM*NC];
// tf32-pre-rounded copies of the inputs (GEMM mainloops become cvt-free)
__device__ __align__(128) float g_xr[(size_t)NM*NC];
__device__ __align__(128) float g_wqkv[(size_t)3*NC*NC];
__device__ __align__(128) float g_wo[(size_t)NC*NC];

// ---------------- PTX helpers ----------------
__device__ __forceinline__ void cpa16(uint32_t s, const void* g) {
    asm volatile("cp.async.cg.shared.global [%0], [%1], 16;" :: "r"(s), "l"(g));
}
__device__ __forceinline__ void cp_commit() { asm volatile("cp.async.commit_group;"); }
template<int N> __device__ __forceinline__ void cp_wait() {
    asm volatile("cp.async.wait_group %0;" :: "n"(N));
}
__device__ __forceinline__ void mma_tf32(float* c,
    uint32_t a0, uint32_t a1, uint32_t a2, uint32_t a3,
    uint32_t b0, uint32_t b1)
{
    asm volatile(
        "mma.sync.aligned.m16n8k8.row.col.f32.tf32.tf32.f32 "
        "{%0,%1,%2,%3},{%4,%5,%6,%7},{%8,%9},{%0,%1,%2,%3};"
        : "+f"(c[0]), "+f"(c[1]), "+f"(c[2]), "+f"(c[3])
        : "r"(a0), "r"(a1), "r"(a2), "r"(a3), "r"(b0), "r"(b1));
}
// rna round to tf32 (result in fp32 layout)
__device__ __forceinline__ float tf32_rna(float x) {
    uint32_t h;
    asm("cvt.rna.tf32.f32 %0, %1;" : "=r"(h) : "f"(x));
    return __uint_as_float(h);
}
__device__ __forceinline__ uint32_t tf32_rna_u(float x) {
    uint32_t h;
    asm("cvt.rna.tf32.f32 %0, %1;" : "=r"(h) : "f"(x));
    return h;
}
__device__ __forceinline__ float ex2f(float x) {
    float y;
    asm("ex2.approx.f32 %0, %1;" : "=f"(y) : "f"(x));
    return y;
}

// ---------------- Pre-round inputs to tf32 ----------------
// sel: 0 -> g_xr, 1 -> g_wqkv, 2 -> g_wo.  n4 float4 elements.
__global__ void __launch_bounds__(256)
round_pre(const float4* __restrict__ src, int n4, int sel)
{
    float* dstf = (sel == 0) ? g_xr : (sel == 1) ? g_wqkv : g_wo;
    int idx = blockIdx.x * 256 + threadIdx.x;
    if (idx < n4) {
        float4 v = src[idx];
        v.x = tf32_rna(v.x); v.y = tf32_rna(v.y);
        v.z = tf32_rna(v.z); v.w = tf32_rna(v.w);
        ((float4*)dstf)[idx] = v;
    }
}

// ---------------- GEMM: C[M,N] = A[M,K] * B[N,K]^T (1x tf32, operands pre-rounded)
// (round-5 configuration: block 128x128x32, warp tile 64x32, 2 CTAs/SM)
// MODE 1: A=g_xr, B=g_wqkv; scatter QKV (rna-rounded) into g_q/g_k/g_v.
// MODE 2: A=g_attn (tf32-rounded by flash), B=g_wo; plain write to Cm.
#define GSTG 9216          // words per stage (4608 + 4608)
#define GPAD 36

template<int MODE>
__global__ void __launch_bounds__(256, 2)
gemm_tf32(float* __restrict__ Cm, int M, int N, int K)
{
    extern __shared__ uint32_t sm[];
    const int tid  = threadIdx.x;
    const int warp = tid >> 5, lane = tid & 31;
    const int gid  = lane >> 2, tig = lane & 3;
    const int wm = warp >> 2, wn = warp & 3;
    const int m0 = blockIdx.y * 128, n0 = blockIdx.x * 128;

    const float* Aeff = (MODE == 1) ? g_xr   : g_attn;
    const float* Beff = (MODE == 1) ? g_wqkv : g_wo;
    const uint32_t smb = (uint32_t)__cvta_generic_to_shared(sm);

    float acc[4][4][4];
#pragma unroll
    for (int i = 0; i < 4; i++)
#pragma unroll
        for (int j = 0; j < 4; j++)
#pragma unroll
            for (int r = 0; r < 4; r++) acc[i][j][r] = 0.f;

    auto load_tile = [&](int stage, int k0) {
        uint32_t base = smb + stage * GSTG * 4;
#pragma unroll
        for (int it = 0; it < 4; it++) {
            int idx = tid + it * 256;            // 1024 float4 per operand
            int r  = idx >> 3;
            int c4 = (idx & 7) * 4;
            cpa16(base + (uint32_t)(r * GPAD + c4) * 4,
                  Aeff + (size_t)(m0 + r) * K + k0 + c4);
            cpa16(base + (uint32_t)(4608 + r * GPAD + c4) * 4,
                  Beff + (size_t)(n0 + r) * K + k0 + c4);
        }
        cp_commit();
    };

    const int NTI = K / 32;
    load_tile(0, 0);

    for (int kt = 0; kt < NTI; kt++) {
        if (kt + 1 < NTI) { load_tile((kt + 1) & 1, (kt + 1) * 32); cp_wait<1>(); }
        else              { cp_wait<0>(); }
        __syncthreads();

        const uint32_t* As = sm + (kt & 1) * GSTG;
        const uint32_t* Bs = As + 4608;
#pragma unroll
        for (int kk = 0; kk < 4; kk++) {
            uint32_t a[4][4], b[4][2];
#pragma unroll
            for (int i = 0; i < 4; i++) {
                const uint32_t* ap = As + (wm * 64 + i * 16 + gid) * GPAD + kk * 8 + tig;
                a[i][0] = ap[0];
                a[i][1] = ap[8 * GPAD];
                a[i][2] = ap[4];
                a[i][3] = ap[8 * GPAD + 4];
            }
#pragma unroll
            for (int j = 0; j < 4; j++) {
                const uint32_t* bp = Bs + (wn * 32 + j * 8 + gid) * GPAD + kk * 8 + tig;
                b[j][0] = bp[0];
                b[j][1] = bp[4];
            }
#pragma unroll
            for (int i = 0; i < 4; i++)
#pragma unroll
                for (int j = 0; j < 4; j++)
                    mma_tf32(acc[i][j], a[i][0], a[i][1], a[i][2], a[i][3],
                             b[j][0], b[j][1]);
        }
        __syncthreads();
    }

    // Epilogue
#pragma unroll
    for (int i = 0; i < 4; i++) {
#pragma unroll
        for (int j = 0; j < 4; j++) {
            int r0 = m0 + wm * 64 + i * 16 + gid;
            int cg = n0 + wn * 32 + j * 8 + tig * 2;
            if (MODE == 2) {
                float2 v0 = make_float2(acc[i][j][0], acc[i][j][1]);
                float2 v1 = make_float2(acc[i][j][2], acc[i][j][3]);
                *(float2*)&Cm[(size_t)r0 * N + cg]       = v0;
                *(float2*)&Cm[(size_t)(r0 + 8) * N + cg] = v1;
            } else {
                int s   = cg >> 10;
                int rem = cg & 1023;
                int h   = rem >> 6;
                int d   = rem & 63;
                float* dst = (s == 0) ? g_q : (s == 1) ? g_k : g_v;
#pragma unroll
                for (int half = 0; half < 2; half++) {
                    int r = r0 + half * 8;
                    int b2 = r >> 11, t = r & 2047;
                    // rna-round to tf32 so flash can use 1x mma exactly
                    float2 v = make_float2(tf32_rna(acc[i][j][half * 2]),
                                           tf32_rna(acc[i][j][half * 2 + 1]));
                    *(float2*)&dst[((size_t)(b2 * NH + h) * NT + t) * NDK + d] = v;
                }
            }
        }
    }
}

// ---------------- Flash attention (1x tf32; 16 rows/warp, kv 64, 2 CTAs/SM) ---
// grid (16 q-tiles of 128, 64 bh), 256 threads (8 warps). Warp w owns q-rows
// w*16..w*16+15.
// smem (uint32 words): Qs[128][68] @0, Ks[2][64][68] @8704/@13056,
//                      Vs[2][64][72] @17408/@22016. Total 26624 w = 106496 B.
// 106.5 KB/CTA -> 2 CTAs/SM -> 16 warps/SM (4/SMSP).
#define KS_OFF0 8704
#define KS_OFF1 13056
#define VS_OFF0 17408
#define VS_OFF1 22016
#define FL_SMEM 106496
#define NKT     32            // 2048 / 64 kv tiles

__global__ void __launch_bounds__(256, 2)
flash_attn()
{
    extern __shared__ uint32_t sm[];
    const int tid  = threadIdx.x;
    const int warp = tid >> 5, lane = tid & 31;
    const int gid  = lane >> 2, tig = lane & 3;
    const int bh = blockIdx.y, qt = blockIdx.x;
    const int qrow = warp * 16;

    const float* Qg = g_q + ((size_t)bh * NT + qt * 128) * NDK;
    const float* Kg = g_k + (size_t)bh * NT * NDK;
    const float* Vg = g_v + (size_t)bh * NT * NDK;

    const uint32_t smb = (uint32_t)__cvta_generic_to_shared(sm);

    auto load_kv = [&](int stage, int kt) {
        uint32_t koff = stage ? KS_OFF1 : KS_OFF0;
        uint32_t voff = stage ? VS_OFF1 : VS_OFF0;
        const float* kp = Kg + (size_t)kt * 64 * NDK;
        const float* vp = Vg + (size_t)kt * 64 * NDK;
#pragma unroll
        for (int it = 0; it < 4; it++) {
            int idx = tid + it * 256;        // 1024 float4 per tile
            int r  = idx >> 4;
            int c4 = (idx & 15) * 4;
            cpa16(smb + (koff + (uint32_t)(r * 68 + c4)) * 4, kp + r * 64 + c4);
            cpa16(smb + (voff + (uint32_t)(r * 72 + c4)) * 4, vp + r * 64 + c4);
        }
    };

    // Prologue: Q (128 rows) + tile0 K/V in group 0
#pragma unroll
    for (int it = 0; it < 8; it++) {
        int idx = tid + it * 256;            // 2048 float4
        int r  = idx >> 4;
        int c4 = (idx & 15) * 4;
        cpa16(smb + (uint32_t)(r * 68 + c4) * 4, Qg + r * 64 + c4);
    }
    load_kv(0, 0);
    cp_commit();

    float o[8][4];
#pragma unroll
    for (int j = 0; j < 8; j++)
#pragma unroll
        for (int r = 0; r < 4; r++) o[j][r] = 0.f;
    float mrow[2] = { -1e30f, -1e30f };
    float lrow[2] = { 0.f, 0.f };

    const float SCL = 0.125f * 1.4426950408889634f;   // (1/sqrt(64)) * log2(e)

    for (int kt = 0; kt < NKT; kt++) {
        const int st = kt & 1;
        if (kt < NKT - 1) { load_kv((kt + 1) & 1, kt + 1); cp_commit(); cp_wait<1>(); }
        else              { cp_wait<0>(); }
        __syncthreads();

        const uint32_t* Ks = sm + (st ? KS_OFF1 : KS_OFF0);
        const uint32_t* Vs = sm + (st ? VS_OFF1 : VS_OFF0);
        const uint32_t* Qs = sm;

        // S = Q * K^T : 16 rows x 64 keys per warp
        float s[8][4];
#pragma unroll
        for (int j = 0; j < 8; j++)
#pragma unroll
            for (int r = 0; r < 4; r++) s[j][r] = 0.f;

#pragma unroll
        for (int kk = 0; kk < 8; kk++) {
            const uint32_t* ap = Qs + (qrow + gid) * 68 + kk * 8 + tig;
            uint32_t a0 = ap[0], a1 = ap[8 * 68], a2 = ap[4], a3 = ap[8 * 68 + 4];
#pragma unroll
            for (int j = 0; j < 8; j++) {
                const uint32_t* bp = Ks + (j * 8 + gid) * 68 + kk * 8 + tig;
                mma_tf32(s[j], a0, a1, a2, a3, bp[0], bp[4]);
            }
        }

        // Online softmax (log2-domain). Row rr=0 -> gid, rr=1 -> gid+8.
        float mnew[2], alpha[2], rsum[2];
#pragma unroll
        for (int rr = 0; rr < 2; rr++) {
            float v = -1e30f;
#pragma unroll
            for (int j = 0; j < 8; j++)
                v = fmaxf(v, fmaxf(s[j][2 * rr], s[j][2 * rr + 1]));
            v = fmaxf(v, __shfl_xor_sync(0xffffffffu, v, 1));
            v = fmaxf(v, __shfl_xor_sync(0xffffffffu, v, 2));
            mnew[rr]  = fmaxf(mrow[rr], v);
            alpha[rr] = ex2f((mrow[rr] - mnew[rr]) * SCL);
            rsum[rr]  = 0.f;
        }
        float m2_0 = mnew[0] * SCL;
        float m2_1 = mnew[1] * SCL;
#pragma unroll
        for (int j = 0; j < 8; j++) {
            float p0 = ex2f(fmaf(s[j][0], SCL, -m2_0));
            float p1 = ex2f(fmaf(s[j][1], SCL, -m2_0));
            float p2 = ex2f(fmaf(s[j][2], SCL, -m2_1));
            float p3 = ex2f(fmaf(s[j][3], SCL, -m2_1));
            s[j][0] = p0; s[j][1] = p1;
            s[j][2] = p2; s[j][3] = p3;
            rsum[0] += p0 + p1;
            rsum[1] += p2 + p3;
        }
#pragma unroll
        for (int rr = 0; rr < 2; rr++) {
            float v = rsum[rr];
            v += __shfl_xor_sync(0xffffffffu, v, 1);
            v += __shfl_xor_sync(0xffffffffu, v, 2);
            lrow[rr] = lrow[rr] * alpha[rr] + v;
            mrow[rr] = mnew[rr];
        }
#pragma unroll
        for (int j = 0; j < 8; j++) {
            o[j][0] *= alpha[0]; o[j][1] *= alpha[0];
            o[j][2] *= alpha[1]; o[j][3] *= alpha[1];
        }

        // O += P * V (1x tf32; V pre-rounded, P rna-rounded after shuffle).
        const int base = lane & ~3;
        const int lo_l = base + (tig >> 1);
        const int hi_l = lo_l + 2;
        const bool odd = (tig & 1);
#pragma unroll
        for (int kk = 0; kk < 8; kk++) {
            float q0 = __shfl_sync(0xffffffffu, s[kk][0], lo_l);
            float q1 = __shfl_sync(0xffffffffu, s[kk][1], lo_l);
            float q2 = __shfl_sync(0xffffffffu, s[kk][2], lo_l);
            float q3 = __shfl_sync(0xffffffffu, s[kk][3], lo_l);
            float r0 = __shfl_sync(0xffffffffu, s[kk][0], hi_l);
            float r1 = __shfl_sync(0xffffffffu, s[kk][1], hi_l);
            float r2 = __shfl_sync(0xffffffffu, s[kk][2], hi_l);
            float r3 = __shfl_sync(0xffffffffu, s[kk][3], hi_l);
            uint32_t a0 = tf32_rna_u(odd ? q1 : q0);
            uint32_t a1 = tf32_rna_u(odd ? q3 : q2);
            uint32_t a2 = tf32_rna_u(odd ? r1 : r0);
            uint32_t a3 = tf32_rna_u(odd ? r3 : r2);
#pragma unroll
            for (int j = 0; j < 8; j++) {
                const uint32_t* bp = Vs + (kk * 8 + tig) * 72 + j * 8 + gid;
                mma_tf32(o[j], a0, a1, a2, a3, bp[0], bp[4 * 72]);
            }
        }
        __syncthreads();
    }

    // Epilogue: O / l -> g_attn[b][t][h*64+d], rna-rounded to tf32 so the
    // output projection's A operand needs no cvt.
    const float inv0 = 1.f / lrow[0];
    const float inv1 = 1.f / lrow[1];
    const int b = bh >> 4, h = bh & 15;
    const int t0 = qt * 128 + qrow + gid;
#pragma unroll
    for (int j = 0; j < 8; j++) {
        int d = j * 8 + tig * 2;
        float2 v0 = make_float2(tf32_rna(o[j][0] * inv0), tf32_rna(o[j][1] * inv0));
        float2 v1 = make_float2(tf32_rna(o[j][2] * inv1), tf32_rna(o[j][3] * inv1));
        *(float2*)&g_attn[(size_t)(b * NT + t0)     * NC + h * 64 + d] = v0;
        *(float2*)&g_attn[(size_t)(b * NT + t0 + 8) * NC + h * 64 + d] = v1;
    }
}

// ---------------- launch ----------------
extern "C" void kernel_launch(void* const* d_in, const int* in_sizes, int n_in,
                              void* d_out, int out_size)
{
    const float* x     = (const float*)d_in[0];
    const float* w_qkv = (const float*)d_in[1];
    const float* w_o   = (const float*)d_in[2];
    float* out = (float*)d_out;

    cudaFuncSetAttribute(gemm_tf32<1>, cudaFuncAttributeMaxDynamicSharedMemorySize, 2 * GSTG * 4);
    cudaFuncSetAttribute(gemm_tf32<2>, cudaFuncAttributeMaxDynamicSharedMemorySize, 2 * GSTG * 4);
    cudaFuncSetAttribute(flash_attn,   cudaFuncAttributeMaxDynamicSharedMemorySize, FL_SMEM);

    // 0) pre-round inputs to tf32 (exact operands everywhere downstream)
    round_pre<<<(NM * NC / 4 + 255) / 256, 256>>>((const float4*)x,     NM * NC / 4,     0);
    round_pre<<<(3 * NC * NC / 4 + 255) / 256, 256>>>((const float4*)w_qkv, 3 * NC * NC / 4, 1);
    round_pre<<<(NC * NC / 4 + 255) / 256, 256>>>((const float4*)w_o,   NC * NC / 4,     2);

    // 1) QKV projection: [8192,1024] x [3072,1024]^T, scatter to g_q/g_k/g_v
    gemm_tf32<1><<<dim3(3072 / 128, NM / 128), 256, 2 * GSTG * 4>>>(
        nullptr, NM, 3 * NC, NC);

    // 2) attention (1x tf32 on pre-rounded operands; 2 CTAs/SM)
    flash_attn<<<dim3(NT / 128, NBH), 256, FL_SMEM>>>();

    // 3) output projection: g_attn[8192,1024] x w_o[1024,1024]^T -> out
    gemm_tf32<2><<<dim3(NC / 128, NM / 128), 256, 2 * GSTG * 4>>>(
        out, NM, NC, NC);
}

// round 8
// speedup vs baseline: 2.0432x; 1.8852x over previous
#include <cuda_runtime.h>
#include <cuda_fp16.h>
#include <cstdint>

// Problem dims (hardcoded; all tile-divisible)
#define NB   4
#define NT   2048
#define NC   1024
#define NH   16
#define NDK  64
#define NBH  (NB*NH)      // 64
#define NM   (NB*NT)      // 8192

// Scratch (static device arrays: allocation-free). All fp16.
__device__ __align__(128) __half g_q[(size_t)NBH*NT*NDK];      // [bh][t][d]
__device__ __align__(128) __half g_k[(size_t)NBH*NT*NDK];      // [bh][t][d]
__device__ __align__(128) __half g_v[(size_t)NBH*NDK*NT];      // [bh][d][t]  (transposed!)
__device__ __align__(128) __half g_attn[(size_t)NM*NC];
__device__ __align__(128) __half g_xh[(size_t)NM*NC];
__device__ __align__(128) __half g_wqkvh[(size_t)3*NC*NC];
__device__ __align__(128) __half g_woh[(size_t)NC*NC];

// ---------------- PTX helpers ----------------
__device__ __forceinline__ void cpa16(uint32_t s, const void* g) {
    asm volatile("cp.async.cg.shared.global [%0], [%1], 16;" :: "r"(s), "l"(g));
}
__device__ __forceinline__ void cp_commit() { asm volatile("cp.async.commit_group;"); }
template<int N> __device__ __forceinline__ void cp_wait() {
    asm volatile("cp.async.wait_group %0;" :: "n"(N));
}
__device__ __forceinline__ void mma_f16(float* c,
    uint32_t a0, uint32_t a1, uint32_t a2, uint32_t a3,
    uint32_t b0, uint32_t b1)
{
    asm volatile(
        "mma.sync.aligned.m16n8k16.row.col.f32.f16.f16.f32 "
        "{%0,%1,%2,%3},{%4,%5,%6,%7},{%8,%9},{%0,%1,%2,%3};"
        : "+f"(c[0]), "+f"(c[1]), "+f"(c[2]), "+f"(c[3])
        : "r"(a0), "r"(a1), "r"(a2), "r"(a3), "r"(b0), "r"(b1));
}
__device__ __forceinline__ float ex2f(float x) {
    float y;
    asm("ex2.approx.f32 %0, %1;" : "=f"(y) : "f"(x));
    return y;
}
__device__ __forceinline__ uint32_t pack_h2(float lo, float hi) {
    __half2 h = __floats2half2_rn(lo, hi);   // .x = lo (low 16 bits)
    return *(uint32_t*)&h;
}

// ---------------- Convert inputs fp32 -> fp16 ----------------
// sel: 0 -> g_xh, 1 -> g_wqkvh, 2 -> g_woh.  n4 = count of float4.
__global__ void __launch_bounds__(256)
conv_half(const float4* __restrict__ src, int n4, int sel)
{
    __half* dst = (sel == 0) ? g_xh : (sel == 1) ? g_wqkvh : g_woh;
    int idx = blockIdx.x * 256 + threadIdx.x;
    if (idx < n4) {
        float4 v = src[idx];
        uint2 o;
        o.x = pack_h2(v.x, v.y);
        o.y = pack_h2(v.z, v.w);
        *(uint2*)&dst[(size_t)idx * 4] = o;
    }
}

// ---------------- GEMM: C[M,N] = A[M,K] * B[N,K]^T (fp16 mma, fp32 accum) -----
// MODE 1: A=g_xh, B=g_wqkvh; scatter QKV into g_q/g_k (row-major) and g_v
//         (transposed [bh][d][t]).
// MODE 2: A=g_attn, B=g_woh; plain fp32 write to Cm.
// Block 128x128x64(halves), 256 threads, warps 2(m) x 4(n), warp tile 64x32.
// smem stage = As[128][36w] + Bs[128][36w] (72 halves/row, 8-half pad).
#define GSTG 9216          // words per stage (4608 + 4608)
#define GPADW 36           // words per padded row (72 halves)

template<int MODE>
__global__ void __launch_bounds__(256, 2)
gemm_f16(float* __restrict__ Cm, int M, int N, int K)
{
    extern __shared__ uint32_t sm[];
    const int tid  = threadIdx.x;
    const int warp = tid >> 5, lane = tid & 31;
    const int gid  = lane >> 2, tig = lane & 3;
    const int wm = warp >> 2, wn = warp & 3;
    const int m0 = blockIdx.y * 128, n0 = blockIdx.x * 128;

    const __half* Aeff = (MODE == 1) ? g_xh    : g_attn;
    const __half* Beff = (MODE == 1) ? g_wqkvh : g_woh;
    const uint32_t smb = (uint32_t)__cvta_generic_to_shared(sm);

    float acc[4][4][4];
#pragma unroll
    for (int i = 0; i < 4; i++)
#pragma unroll
        for (int j = 0; j < 4; j++)
#pragma unroll
            for (int r = 0; r < 4; r++) acc[i][j][r] = 0.f;

    auto load_tile = [&](int stage, int k0) {
        uint32_t base = smb + stage * GSTG * 4;
        // 128 rows x 64 halves = 8 chunks of 16B per row, per operand
#pragma unroll
        for (int it = 0; it < 4; it++) {
            int idx = tid + it * 256;
            int r = idx >> 3;
            int c = idx & 7;                       // 16B chunk (8 halves)
            cpa16(base + (uint32_t)(r * GPADW + c * 4) * 4,
                  Aeff + (size_t)(m0 + r) * K + k0 + c * 8);
            cpa16(base + (uint32_t)(4608 + r * GPADW + c * 4) * 4,
                  Beff + (size_t)(n0 + r) * K + k0 + c * 8);
        }
        cp_commit();
    };

    const int NTI = K / 64;
    load_tile(0, 0);

    for (int kt = 0; kt < NTI; kt++) {
        if (kt + 1 < NTI) { load_tile((kt + 1) & 1, (kt + 1) * 64); cp_wait<1>(); }
        else              { cp_wait<0>(); }
        __syncthreads();

        const uint32_t* As = sm + (kt & 1) * GSTG;
        const uint32_t* Bs = As + 4608;
#pragma unroll
        for (int kk = 0; kk < 4; kk++) {           // 4 x k16
            uint32_t a[4][4], b[4][2];
#pragma unroll
            for (int i = 0; i < 4; i++) {
                const uint32_t* ap = As + (wm * 64 + i * 16 + gid) * GPADW + kk * 8 + tig;
                a[i][0] = ap[0];
                a[i][1] = ap[8 * GPADW];
                a[i][2] = ap[4];
                a[i][3] = ap[8 * GPADW + 4];
            }
#pragma unroll
            for (int j = 0; j < 4; j++) {
                const uint32_t* bp = Bs + (wn * 32 + j * 8 + gid) * GPADW + kk * 8 + tig;
                b[j][0] = bp[0];
                b[j][1] = bp[4];
            }
#pragma unroll
            for (int i = 0; i < 4; i++)
#pragma unroll
                for (int j = 0; j < 4; j++)
                    mma_f16(acc[i][j], a[i][0], a[i][1], a[i][2], a[i][3],
                            b[j][0], b[j][1]);
        }
        __syncthreads();
    }

    // Epilogue
#pragma unroll
    for (int i = 0; i < 4; i++) {
#pragma unroll
        for (int j = 0; j < 4; j++) {
            int r0 = m0 + wm * 64 + i * 16 + gid;
            int cg = n0 + wn * 32 + j * 8 + tig * 2;
            if (MODE == 2) {
                float2 v0 = make_float2(acc[i][j][0], acc[i][j][1]);
                float2 v1 = make_float2(acc[i][j][2], acc[i][j][3]);
                *(float2*)&Cm[(size_t)r0 * N + cg]       = v0;
                *(float2*)&Cm[(size_t)(r0 + 8) * N + cg] = v1;
            } else {
                int s   = cg >> 10;
                int rem = cg & 1023;
                int h   = rem >> 6;
                int d   = rem & 63;
#pragma unroll
                for (int half_ = 0; half_ < 2; half_++) {
                    int r = r0 + half_ * 8;
                    int b2 = r >> 11, t = r & 2047;
                    float e0 = acc[i][j][half_ * 2];
                    float e1 = acc[i][j][half_ * 2 + 1];
                    if (s == 2) {
                        // V transposed: [bh][d][t]
                        size_t basev = (size_t)(b2 * NH + h) * NDK;
                        g_v[(basev + d)     * NT + t] = __float2half_rn(e0);
                        g_v[(basev + d + 1) * NT + t] = __float2half_rn(e1);
                    } else {
                        __half* dst = (s == 0) ? g_q : g_k;
                        __half2 v = __floats2half2_rn(e0, e1);
                        *(__half2*)&dst[((size_t)(b2 * NH + h) * NT + t) * NDK + d] = v;
                    }
                }
            }
        }
    }
}

// ---------------- Flash attention (fp16 mma; 16 rows/warp, kv 64) -------------
// grid (16 q-tiles of 128, 64 bh), 256 threads (8 warps).
// smem words: Qs[128][36] @0, Ks[2][64][36] @4608/@6912,
//             VsT[2][64][36] @9216/@11520 (VsT[d][kv]).  Total 13824 w = 55296 B.
#define KS_OFF0 4608
#define KS_OFF1 6912
#define VS_OFF0 9216
#define VS_OFF1 11520
#define FL_SMEM 55296
#define NKT     32            // 2048 / 64 kv tiles

__global__ void __launch_bounds__(256, 2)
flash_attn()
{
    extern __shared__ uint32_t sm[];
    const int tid  = threadIdx.x;
    const int warp = tid >> 5, lane = tid & 31;
    const int gid  = lane >> 2, tig = lane & 3;
    const int bh = blockIdx.y, qt = blockIdx.x;
    const int qrow = warp * 16;

    const __half* Qg  = g_q + ((size_t)bh * NT + qt * 128) * NDK;
    const __half* Kg  = g_k + (size_t)bh * NT * NDK;
    const __half* VgT = g_v + (size_t)bh * NDK * NT;   // [d][t]

    const uint32_t smb = (uint32_t)__cvta_generic_to_shared(sm);

    auto load_kv = [&](int stage, int kt) {
        uint32_t koff = stage ? KS_OFF1 : KS_OFF0;
        uint32_t voff = stage ? VS_OFF1 : VS_OFF0;
        const __half* kp = Kg + (size_t)kt * 64 * NDK;      // 64 keys x 64 d
        const __half* vp = VgT + (size_t)kt * 64;           // 64 d-rows x 64 t
#pragma unroll
        for (int it = 0; it < 2; it++) {
            int idx = tid + it * 256;        // 512 chunks per tile
            int r = idx >> 3;
            int c = idx & 7;
            cpa16(smb + (koff + (uint32_t)(r * 36 + c * 4)) * 4, kp + r * 64 + c * 8);
            cpa16(smb + (voff + (uint32_t)(r * 36 + c * 4)) * 4, vp + (size_t)r * NT + c * 8);
        }
    };

    // Prologue: Q (128 rows x 64 halves) + tile0 K/V in group 0
#pragma unroll
    for (int it = 0; it < 4; it++) {
        int idx = tid + it * 256;            // 1024 chunks
        int r = idx >> 3;
        int c = idx & 7;
        cpa16(smb + (uint32_t)(r * 36 + c * 4) * 4, Qg + r * 64 + c * 8);
    }
    load_kv(0, 0);
    cp_commit();

    float o[8][4];
#pragma unroll
    for (int j = 0; j < 8; j++)
#pragma unroll
        for (int r = 0; r < 4; r++) o[j][r] = 0.f;
    float mrow[2] = { -1e30f, -1e30f };
    float lrow[2] = { 0.f, 0.f };

    const float SCL = 0.125f * 1.4426950408889634f;   // (1/sqrt(64)) * log2(e)

    for (int kt = 0; kt < NKT; kt++) {
        const int st = kt & 1;
        if (kt < NKT - 1) { load_kv((kt + 1) & 1, kt + 1); cp_commit(); cp_wait<1>(); }
        else              { cp_wait<0>(); }
        __syncthreads();

        const uint32_t* Ks = sm + (st ? KS_OFF1 : KS_OFF0);
        const uint32_t* Vs = sm + (st ? VS_OFF1 : VS_OFF0);
        const uint32_t* Qs = sm;

        // S = Q * K^T : 16 rows x 64 keys per warp (4 x k16 steps)
        float s[8][4];
#pragma unroll
        for (int j = 0; j < 8; j++)
#pragma unroll
            for (int r = 0; r < 4; r++) s[j][r] = 0.f;

#pragma unroll
        for (int kk = 0; kk < 4; kk++) {
            const uint32_t* ap = Qs + (qrow + gid) * 36 + kk * 8 + tig;
            uint32_t a0 = ap[0], a1 = ap[8 * 36], a2 = ap[4], a3 = ap[8 * 36 + 4];
#pragma unroll
            for (int j = 0; j < 8; j++) {
                const uint32_t* bp = Ks + (j * 8 + gid) * 36 + kk * 8 + tig;
                mma_f16(s[j], a0, a1, a2, a3, bp[0], bp[4]);
            }
        }

        // Online softmax (log2-domain). Row rr=0 -> gid, rr=1 -> gid+8.
        float mnew[2], alpha[2], rsum[2];
#pragma unroll
        for (int rr = 0; rr < 2; rr++) {
            float v = -1e30f;
#pragma unroll
            for (int j = 0; j < 8; j++)
                v = fmaxf(v, fmaxf(s[j][2 * rr], s[j][2 * rr + 1]));
            v = fmaxf(v, __shfl_xor_sync(0xffffffffu, v, 1));
            v = fmaxf(v, __shfl_xor_sync(0xffffffffu, v, 2));
            mnew[rr]  = fmaxf(mrow[rr], v);
            alpha[rr] = ex2f((mrow[rr] - mnew[rr]) * SCL);
            rsum[rr]  = 0.f;
        }
        float m2_0 = mnew[0] * SCL;
        float m2_1 = mnew[1] * SCL;
#pragma unroll
        for (int j = 0; j < 8; j++) {
            float p0 = ex2f(fmaf(s[j][0], SCL, -m2_0));
            float p1 = ex2f(fmaf(s[j][1], SCL, -m2_0));
            float p2 = ex2f(fmaf(s[j][2], SCL, -m2_1));
            float p3 = ex2f(fmaf(s[j][3], SCL, -m2_1));
            s[j][0] = p0; s[j][1] = p1;
            s[j][2] = p2; s[j][3] = p3;
            rsum[0] += p0 + p1;
            rsum[1] += p2 + p3;
        }
#pragma unroll
        for (int rr = 0; rr < 2; rr++) {
            float v = rsum[rr];
            v += __shfl_xor_sync(0xffffffffu, v, 1);
            v += __shfl_xor_sync(0xffffffffu, v, 2);
            lrow[rr] = lrow[rr] * alpha[rr] + v;
            mrow[rr] = mnew[rr];
        }
#pragma unroll
        for (int j = 0; j < 8; j++) {
            o[j][0] *= alpha[0]; o[j][1] *= alpha[0];
            o[j][2] *= alpha[1]; o[j][3] *= alpha[1];
        }

        // O += P * V.  fp16 A-frag layout == S C-frag layout: NO shuffles,
        // just f32->f16x2 packs.  B from transposed VsT[d][kv].
#pragma unroll
        for (int kk = 0; kk < 4; kk++) {           // kv 16-window = chunks 2kk,2kk+1
            uint32_t a0 = pack_h2(s[2 * kk][0],     s[2 * kk][1]);
            uint32_t a1 = pack_h2(s[2 * kk][2],     s[2 * kk][3]);
            uint32_t a2 = pack_h2(s[2 * kk + 1][0], s[2 * kk + 1][1]);
            uint32_t a3 = pack_h2(s[2 * kk + 1][2], s[2 * kk + 1][3]);
#pragma unroll
            for (int j = 0; j < 8; j++) {
                const uint32_t* bp = Vs + (j * 8 + gid) * 36 + kk * 8 + tig;
                mma_f16(o[j], a0, a1, a2, a3, bp[0], bp[4]);
            }
        }
        __syncthreads();
    }

    // Epilogue: O / l -> g_attn[b][t][h*64+d] (fp16)
    const float inv0 = 1.f / lrow[0];
    const float inv1 = 1.f / lrow[1];
    const int b = bh >> 4, h = bh & 15;
    const int t0 = qt * 128 + qrow + gid;
#pragma unroll
    for (int j = 0; j < 8; j++) {
        int d = j * 8 + tig * 2;
        __half2 v0 = __floats2half2_rn(o[j][0] * inv0, o[j][1] * inv0);
        __half2 v1 = __floats2half2_rn(o[j][2] * inv1, o[j][3] * inv1);
        *(__half2*)&g_attn[(size_t)(b * NT + t0)     * NC + h * 64 + d] = v0;
        *(__half2*)&g_attn[(size_t)(b * NT + t0 + 8) * NC + h * 64 + d] = v1;
    }
}

// ---------------- launch ----------------
extern "C" void kernel_launch(void* const* d_in, const int* in_sizes, int n_in,
                              void* d_out, int out_size)
{
    const float* x     = (const float*)d_in[0];
    const float* w_qkv = (const float*)d_in[1];
    const float* w_o   = (const float*)d_in[2];
    float* out = (float*)d_out;

    cudaFuncSetAttribute(gemm_f16<1>, cudaFuncAttributeMaxDynamicSharedMemorySize, 2 * GSTG * 4);
    cudaFuncSetAttribute(gemm_f16<2>, cudaFuncAttributeMaxDynamicSharedMemorySize, 2 * GSTG * 4);
    cudaFuncSetAttribute(flash_attn,  cudaFuncAttributeMaxDynamicSharedMemorySize, FL_SMEM);

    // 0) convert inputs to fp16
    conv_half<<<(NM * NC / 4 + 255) / 256, 256>>>((const float4*)x,     NM * NC / 4,     0);
    conv_half<<<(3 * NC * NC / 4 + 255) / 256, 256>>>((const float4*)w_qkv, 3 * NC * NC / 4, 1);
    conv_half<<<(NC * NC / 4 + 255) / 256, 256>>>((const float4*)w_o,   NC * NC / 4,     2);

    // 1) QKV projection: [8192,1024] x [3072,1024]^T -> g_q/g_k/g_v(T)
    gemm_f16<1><<<dim3(3072 / 128, NM / 128), 256, 2 * GSTG * 4>>>(
        nullptr, NM, 3 * NC, NC);

    // 2) attention
    flash_attn<<<dim3(NT / 128, NBH), 256, FL_SMEM>>>();

    // 3) output projection: g_attn[8192,1024] x w_o[1024,1024]^T -> out (fp32)
    gemm_f16<2><<<dim3(NC / 128, NM / 128), 256, 2 * GSTG * 4>>>(
        out, NM, NC, NC);
}